// round 1
// baseline (speedup 1.0000x reference)
#include <cuda_runtime.h>
#include <math.h>

// ---------------- problem constants ----------------
#define S_LEN  2048
#define BATCH  2
#define DMODEL 768
#define NH     12
#define NKV    4
#define HDIM   64
#define FFDIM  3072
#define NLAYER 2
#define M_TOK  (BATCH * S_LEN)   // 4096 tokens

// ---------------- scratch (device globals; no allocation allowed) ----------
__device__ float g_h   [M_TOK * DMODEL];
__device__ float g_q   [M_TOK * DMODEL];
__device__ float g_k   [M_TOK * NKV * HDIM];
__device__ float g_v   [M_TOK * NKV * HDIM];
__device__ float g_att [M_TOK * DMODEL];
__device__ float g_x1  [M_TOK * DMODEL];
__device__ float g_x2  [M_TOK * DMODEL];
__device__ float g_gate[M_TOK * FFDIM];
__device__ float g_cosT[S_LEN * 32];
__device__ float g_sinT[S_LEN * 32];

// ---------------- RoPE tables ----------------
__global__ void rope_table_kernel(float* __restrict__ cosT, float* __restrict__ sinT) {
    int idx = blockIdx.x * blockDim.x + threadIdx.x;
    if (idx >= S_LEN * 32) return;
    int p = idx >> 5, i = idx & 31;
    double f  = exp(-((double)(2 * i) / 64.0) * log(10000.0));
    float ang = (float)p * (float)f;      // fp32 angle rounding, like the reference
    cosT[idx] = (float)cos((double)ang);
    sinT[idx] = (float)sin((double)ang);
}

// ---------------- RMSNorm (one block per row) ----------------
__global__ void rmsnorm_kernel(const float* __restrict__ x,
                               const float* __restrict__ w,
                               float* __restrict__ o) {
    int row = blockIdx.x;
    const float* xr = x + (size_t)row * DMODEL;
    float v[3];
    float s = 0.f;
#pragma unroll
    for (int t = 0; t < 3; t++) {
        v[t] = xr[threadIdx.x + t * 256];
        s += v[t] * v[t];
    }
#pragma unroll
    for (int off = 16; off > 0; off >>= 1) s += __shfl_xor_sync(0xffffffffu, s, off);
    __shared__ float red[8];
    if ((threadIdx.x & 31) == 0) red[threadIdx.x >> 5] = s;
    __syncthreads();
    float tot = 0.f;
#pragma unroll
    for (int i = 0; i < 8; i++) tot += red[i];
    float scale = rsqrtf(tot * (1.0f / (float)DMODEL) + 1e-6f);
    float* orow = o + (size_t)row * DMODEL;
#pragma unroll
    for (int t = 0; t < 3; t++) {
        int c = threadIdx.x + t * 256;
        orow[c] = v[t] * scale * w[c];
    }
}

// ---------------- RoPE apply (one block per token) ----------------
__global__ void rope_kernel(float* __restrict__ q, float* __restrict__ k,
                            const float* __restrict__ cosT,
                            const float* __restrict__ sinT) {
    int token = blockIdx.x;
    int pos = token & (S_LEN - 1);
    for (int t = threadIdx.x; t < (NH + NKV) * 32; t += 256) {
        int i  = t & 31;
        int hh = t >> 5;   // 0..11 = q heads, 12..15 = k heads
        float c = cosT[pos * 32 + i];
        float s = sinT[pos * 32 + i];
        float* base = (hh < NH) ? (q + (size_t)token * DMODEL + hh * HDIM)
                                : (k + (size_t)token * (NKV * HDIM) + (hh - NH) * HDIM);
        float t0 = base[2 * i], t1 = base[2 * i + 1];
        base[2 * i]     = t0 * c - t1 * s;
        base[2 * i + 1] = t0 * s + t1 * c;
    }
}

// ---------------- SGEMM 128x128x16, 8x8 micro-tiles, fused epilogues -------
// mode: 0 = plain, 1 = silu(acc), 2 = acc * aux[idx], 3 = acc + aux[idx]
// blockIdx.z selects (B0,O0) vs (B1,O1) so two same-shape GEMMs fuse into one
// launch (used for the K/V projections).
__global__ void __launch_bounds__(256, 2) gemm_kernel(
    const float* __restrict__ A,
    const float* __restrict__ B0, const float* __restrict__ B1,
    const float* __restrict__ aux,
    float* __restrict__ O0, float* __restrict__ O1,
    int N, int K, int mode) {
    const float* B = blockIdx.z ? B1 : B0;
    float*       O = blockIdx.z ? O1 : O0;
    __shared__ float As[16][128];
    __shared__ float Bs[16][128];
    const int tid = threadIdx.x;
    const int tr = tid >> 4, tc = tid & 15;
    const int rowBase = blockIdx.y * 128;
    const int colBase = blockIdx.x * 128;

    float acc[8][8];
#pragma unroll
    for (int i = 0; i < 8; i++)
#pragma unroll
        for (int j = 0; j < 8; j++) acc[i][j] = 0.f;

    const int ar  = tid >> 2;
    const int ac4 = (tid & 3) << 2;
    const int br  = tid >> 5;
    const int bc4 = (tid & 31) << 2;

    for (int k0 = 0; k0 < K; k0 += 16) {
#pragma unroll
        for (int t = 0; t < 2; t++) {
            int arr = ar + t * 64;
            float4 av = *(const float4*)(A + (size_t)(rowBase + arr) * K + (k0 + ac4));
            As[ac4 + 0][arr] = av.x; As[ac4 + 1][arr] = av.y;
            As[ac4 + 2][arr] = av.z; As[ac4 + 3][arr] = av.w;
            int brr = br + t * 8;
            float4 bv = *(const float4*)(B + (size_t)(k0 + brr) * N + (colBase + bc4));
            *(float4*)(&Bs[brr][bc4]) = bv;
        }
        __syncthreads();
#pragma unroll
        for (int kk = 0; kk < 16; kk++) {
            float a[8], b[8];
#pragma unroll
            for (int i = 0; i < 8; i++) a[i] = As[kk][tr * 8 + i];
#pragma unroll
            for (int j = 0; j < 8; j++) b[j] = Bs[kk][tc * 8 + j];
#pragma unroll
            for (int i = 0; i < 8; i++)
#pragma unroll
                for (int j = 0; j < 8; j++)
                    acc[i][j] = fmaf(a[i], b[j], acc[i][j]);
        }
        __syncthreads();
    }
#pragma unroll
    for (int i = 0; i < 8; i++) {
        int row = rowBase + tr * 8 + i;
#pragma unroll
        for (int j = 0; j < 8; j++) {
            int col = colBase + tc * 8 + j;
            size_t idx = (size_t)row * N + col;
            float val = acc[i][j];
            if (mode == 1)      val = val / (1.f + __expf(-val));
            else if (mode == 2) val = val * aux[idx];
            else if (mode == 3) val = val + aux[idx];
            O[idx] = val;
        }
    }
}

// ---------------- Flash attention (fp32, causal, GQA) ----------------
#define FPAD 65
#define FLASH_SMEM (4 * 64 * FPAD * 4)

__global__ void __launch_bounds__(256) flash_kernel(
    const float* __restrict__ q, const float* __restrict__ k,
    const float* __restrict__ v, float* __restrict__ o) {
    extern __shared__ float sm[];
    float* Qs = sm;
    float* Ks = sm + 64 * FPAD;
    float* Vs = sm + 2 * 64 * FPAD;
    float* Ps = sm + 3 * 64 * FPAD;

    const int qb  = (gridDim.x - 1) - blockIdx.x;  // heavy blocks first
    const int bh  = blockIdx.y;
    const int b   = bh / NH;
    const int h   = bh % NH;
    const int kvh = h / (NH / NKV);
    const int tid = threadIdx.x;
    const int ty  = tid >> 4, tx = tid & 15;

    // load Q tile [64 x 64]
#pragma unroll
    for (int t = 0; t < 4; t++) {
        int fi = tid + t * 256;
        int r = fi >> 4, c4 = (fi & 15) << 2;
        const float* src = q + ((size_t)((b * S_LEN + qb * 64 + r) * NH + h)) * HDIM + c4;
        float4 vv = *(const float4*)src;
        float* dst = Qs + r * FPAD + c4;
        dst[0] = vv.x; dst[1] = vv.y; dst[2] = vv.z; dst[3] = vv.w;
    }

    float m[4], l[4], oa[4][4];
#pragma unroll
    for (int i = 0; i < 4; i++) {
        m[i] = -1e30f; l[i] = 0.f;
#pragma unroll
        for (int j = 0; j < 4; j++) oa[i][j] = 0.f;
    }

    for (int kb = 0; kb <= qb; kb++) {
        __syncthreads();   // prior iteration's P/V readers done before overwrite
#pragma unroll
        for (int t = 0; t < 4; t++) {
            int fi = tid + t * 256;
            int r = fi >> 4, c4 = (fi & 15) << 2;
            size_t goff = ((size_t)((b * S_LEN + kb * 64 + r) * NKV + kvh)) * HDIM + c4;
            float4 k4 = *(const float4*)(k + goff);
            float* kd = Ks + r * FPAD + c4;
            kd[0] = k4.x; kd[1] = k4.y; kd[2] = k4.z; kd[3] = k4.w;
            float4 v4 = *(const float4*)(v + goff);
            float* vd = Vs + r * FPAD + c4;
            vd[0] = v4.x; vd[1] = v4.y; vd[2] = v4.z; vd[3] = v4.w;
        }
        __syncthreads();

        float sc[4][4];
#pragma unroll
        for (int i = 0; i < 4; i++)
#pragma unroll
            for (int j = 0; j < 4; j++) sc[i][j] = 0.f;

#pragma unroll 8
        for (int d = 0; d < 64; d++) {
            float qf[4], kf[4];
#pragma unroll
            for (int i = 0; i < 4; i++) qf[i] = Qs[(ty * 4 + i) * FPAD + d];
#pragma unroll
            for (int j = 0; j < 4; j++) kf[j] = Ks[(tx * 4 + j) * FPAD + d];
#pragma unroll
            for (int i = 0; i < 4; i++)
#pragma unroll
                for (int j = 0; j < 4; j++)
                    sc[i][j] = fmaf(qf[i], kf[j], sc[i][j]);
        }

        const bool diag = (kb == qb);
#pragma unroll
        for (int i = 0; i < 4; i++)
#pragma unroll
            for (int j = 0; j < 4; j++) {
                float val = sc[i][j] * 0.125f;      // 1/sqrt(64)
                if (diag && (tx * 4 + j > ty * 4 + i)) val = -1e30f;
                sc[i][j] = val;
            }

#pragma unroll
        for (int i = 0; i < 4; i++) {
            float rm = fmaxf(fmaxf(sc[i][0], sc[i][1]), fmaxf(sc[i][2], sc[i][3]));
#pragma unroll
            for (int off = 8; off > 0; off >>= 1)
                rm = fmaxf(rm, __shfl_xor_sync(0xffffffffu, rm, off));
            float mnew  = fmaxf(m[i], rm);
            float alpha = __expf(m[i] - mnew);
            m[i] = mnew;
            float s0 = 0.f;
#pragma unroll
            for (int j = 0; j < 4; j++) {
                float p = __expf(sc[i][j] - mnew);
                sc[i][j] = p;
                s0 += p;
            }
#pragma unroll
            for (int off = 8; off > 0; off >>= 1)
                s0 += __shfl_xor_sync(0xffffffffu, s0, off);
            l[i] = l[i] * alpha + s0;
#pragma unroll
            for (int j = 0; j < 4; j++) oa[i][j] *= alpha;
        }

        // stage P to smem for the PV GEMM
#pragma unroll
        for (int i = 0; i < 4; i++)
#pragma unroll
            for (int j = 0; j < 4; j++)
                Ps[(ty * 4 + i) * FPAD + tx * 4 + j] = sc[i][j];
        __syncthreads();

#pragma unroll 8
        for (int c = 0; c < 64; c++) {
            float pf[4], vf[4];
#pragma unroll
            for (int i = 0; i < 4; i++) pf[i] = Ps[(ty * 4 + i) * FPAD + c];
#pragma unroll
            for (int j = 0; j < 4; j++) vf[j] = Vs[c * FPAD + tx * 4 + j];
#pragma unroll
            for (int i = 0; i < 4; i++)
#pragma unroll
                for (int j = 0; j < 4; j++)
                    oa[i][j] = fmaf(pf[i], vf[j], oa[i][j]);
        }
    }

#pragma unroll
    for (int i = 0; i < 4; i++) {
        float inv = 1.f / l[i];
        int row = b * S_LEN + qb * 64 + ty * 4 + i;
        float* dst = o + ((size_t)(row * NH + h)) * HDIM + tx * 4;
#pragma unroll
        for (int j = 0; j < 4; j++) dst[j] = oa[i][j] * inv;
    }
}

// ---------------- launch ----------------
extern "C" void kernel_launch(void* const* d_in, const int* in_sizes, int n_in,
                              void* d_out, int out_size) {
    const float* x  = (const float*)d_in[0];
    const float* Wq = (const float*)d_in[1];
    const float* Wk = (const float*)d_in[2];
    const float* Wv = (const float*)d_in[3];
    const float* Wo = (const float*)d_in[4];
    const float* an = (const float*)d_in[5];
    const float* w0 = (const float*)d_in[6];
    const float* w1 = (const float*)d_in[7];
    const float* w2 = (const float*)d_in[8];
    const float* sn = (const float*)d_in[9];
    const float* on = (const float*)d_in[10];
    float* out = (float*)d_out;

    float *h, *q, *k, *v, *att, *x1, *x2, *gate, *cosT, *sinT;
    cudaGetSymbolAddress((void**)&h,    g_h);
    cudaGetSymbolAddress((void**)&q,    g_q);
    cudaGetSymbolAddress((void**)&k,    g_k);
    cudaGetSymbolAddress((void**)&v,    g_v);
    cudaGetSymbolAddress((void**)&att,  g_att);
    cudaGetSymbolAddress((void**)&x1,   g_x1);
    cudaGetSymbolAddress((void**)&x2,   g_x2);
    cudaGetSymbolAddress((void**)&gate, g_gate);
    cudaGetSymbolAddress((void**)&cosT, g_cosT);
    cudaGetSymbolAddress((void**)&sinT, g_sinT);

    cudaFuncSetAttribute(flash_kernel,
                         cudaFuncAttributeMaxDynamicSharedMemorySize, FLASH_SMEM);

    rope_table_kernel<<<(S_LEN * 32 + 255) / 256, 256>>>(cosT, sinT);

    const dim3 gN768 (DMODEL / 128, M_TOK / 128, 1);
    const dim3 gKV   ((NKV * HDIM) / 128, M_TOK / 128, 2);
    const dim3 gFF   (FFDIM / 128, M_TOK / 128, 1);

    const float* xin = x;
    for (int l = 0; l < NLAYER; l++) {
        const float* Wq_l = Wq + (size_t)l * DMODEL * DMODEL;
        const float* Wk_l = Wk + (size_t)l * DMODEL * (NKV * HDIM);
        const float* Wv_l = Wv + (size_t)l * DMODEL * (NKV * HDIM);
        const float* Wo_l = Wo + (size_t)l * DMODEL * DMODEL;
        const float* w0_l = w0 + (size_t)l * DMODEL * FFDIM;
        const float* w1_l = w1 + (size_t)l * DMODEL * FFDIM;
        const float* w2_l = w2 + (size_t)l * FFDIM * DMODEL;

        // h = rmsnorm(x, an)
        rmsnorm_kernel<<<M_TOK, 256>>>(xin, an + l * DMODEL, h);
        // q/k/v projections
        gemm_kernel<<<gN768, 256>>>(h, Wq_l, Wq_l, nullptr, q, q, DMODEL, DMODEL, 0);
        gemm_kernel<<<gKV,   256>>>(h, Wk_l, Wv_l, nullptr, k, v, NKV * HDIM, DMODEL, 0);
        // rope on q, k
        rope_kernel<<<M_TOK, 256>>>(q, k, cosT, sinT);
        // attention
        flash_kernel<<<dim3(S_LEN / 64, BATCH * NH), 256, FLASH_SMEM>>>(q, k, v, att);
        // h2 = x + att @ Wo
        gemm_kernel<<<gN768, 256>>>(att, Wo_l, Wo_l, xin, x1, x1, DMODEL, DMODEL, 3);
        // n = rmsnorm(h2, sn)
        rmsnorm_kernel<<<M_TOK, 256>>>(x1, sn + l * DMODEL, h);
        // gate = silu(n @ w0); gate *= (n @ w1)
        gemm_kernel<<<gFF, 256>>>(h, w0_l, w0_l, nullptr, gate, gate, FFDIM, DMODEL, 1);
        gemm_kernel<<<gFF, 256>>>(h, w1_l, w1_l, gate, gate, gate, FFDIM, DMODEL, 2);
        // x = h2 + gate @ w2
        gemm_kernel<<<gN768, 256>>>(gate, w2_l, w2_l, x1, x2, x2, DMODEL, FFDIM, 3);
        xin = x2;
    }
    // final rmsnorm -> d_out
    rmsnorm_kernel<<<M_TOK, 256>>>(x2, on, out);
}

// round 2
// speedup vs baseline: 2.6078x; 2.6078x over previous
#include <cuda_runtime.h>
#include <math.h>
#include <stdint.h>

// ---------------- problem constants ----------------
#define S_LEN  2048
#define BATCH  2
#define DMODEL 768
#define NH     12
#define NKV    4
#define HDIM   64
#define FFDIM  3072
#define NLAYER 2
#define M_TOK  (BATCH * S_LEN)   // 4096 tokens

// ---------------- scratch (device globals; no allocation allowed) ----------
__device__ float g_h   [M_TOK * DMODEL];
__device__ float g_q   [M_TOK * DMODEL];
__device__ float g_k   [M_TOK * NKV * HDIM];
__device__ float g_v   [M_TOK * NKV * HDIM];
__device__ float g_att [M_TOK * DMODEL];
__device__ float g_x1  [M_TOK * DMODEL];
__device__ float g_x2  [M_TOK * DMODEL];
__device__ float g_gate[M_TOK * FFDIM];
__device__ float g_cosT[S_LEN * 32];
__device__ float g_sinT[S_LEN * 32];

// ---------------- helpers ----------------
__device__ __forceinline__ float tf32r(float x) {
    uint32_t u;
    asm("cvt.rna.tf32.f32 %0, %1;" : "=r"(u) : "f"(x));
    return __uint_as_float(u);
}
__device__ __forceinline__ float4 tf32r4(float4 v) {
    float4 r;
    r.x = tf32r(v.x); r.y = tf32r(v.y); r.z = tf32r(v.z); r.w = tf32r(v.w);
    return r;
}
__device__ __forceinline__ void mma_tf32(float (&c)[4],
                                         uint32_t a0, uint32_t a1, uint32_t a2, uint32_t a3,
                                         uint32_t b0, uint32_t b1) {
    asm volatile(
        "mma.sync.aligned.m16n8k8.row.col.f32.tf32.tf32.f32 "
        "{%0,%1,%2,%3}, {%4,%5,%6,%7}, {%8,%9}, {%0,%1,%2,%3};"
        : "+f"(c[0]), "+f"(c[1]), "+f"(c[2]), "+f"(c[3])
        : "r"(a0), "r"(a1), "r"(a2), "r"(a3), "r"(b0), "r"(b1));
}
#define FU(x) __float_as_uint(x)

// ---------------- RoPE tables ----------------
__global__ void rope_table_kernel(float* __restrict__ cosT, float* __restrict__ sinT) {
    int idx = blockIdx.x * blockDim.x + threadIdx.x;
    if (idx >= S_LEN * 32) return;
    int p = idx >> 5, i = idx & 31;
    double f  = exp(-((double)(2 * i) / 64.0) * log(10000.0));
    float ang = (float)p * (float)f;
    cosT[idx] = (float)cos((double)ang);
    sinT[idx] = (float)sin((double)ang);
}

// ---------------- RMSNorm (one block per row) ----------------
__global__ void rmsnorm_kernel(const float* __restrict__ x,
                               const float* __restrict__ w,
                               float* __restrict__ o) {
    int row = blockIdx.x;
    const float* xr = x + (size_t)row * DMODEL;
    float v[3];
    float s = 0.f;
#pragma unroll
    for (int t = 0; t < 3; t++) {
        v[t] = xr[threadIdx.x + t * 256];
        s += v[t] * v[t];
    }
#pragma unroll
    for (int off = 16; off > 0; off >>= 1) s += __shfl_xor_sync(0xffffffffu, s, off);
    __shared__ float red[8];
    if ((threadIdx.x & 31) == 0) red[threadIdx.x >> 5] = s;
    __syncthreads();
    float tot = 0.f;
#pragma unroll
    for (int i = 0; i < 8; i++) tot += red[i];
    float scale = rsqrtf(tot * (1.0f / (float)DMODEL) + 1e-6f);
    float* orow = o + (size_t)row * DMODEL;
#pragma unroll
    for (int t = 0; t < 3; t++) {
        int c = threadIdx.x + t * 256;
        orow[c] = v[t] * scale * w[c];
    }
}

// ---------------- RoPE apply (one block per token) ----------------
__global__ void rope_kernel(float* __restrict__ q, float* __restrict__ k,
                            const float* __restrict__ cosT,
                            const float* __restrict__ sinT) {
    int token = blockIdx.x;
    int pos = token & (S_LEN - 1);
    for (int t = threadIdx.x; t < (NH + NKV) * 32; t += 256) {
        int i  = t & 31;
        int hh = t >> 5;   // 0..11 = q heads, 12..15 = k heads
        float c = cosT[pos * 32 + i];
        float s = sinT[pos * 32 + i];
        float* base = (hh < NH) ? (q + (size_t)token * DMODEL + hh * HDIM)
                                : (k + (size_t)token * (NKV * HDIM) + (hh - NH) * HDIM);
        float t0 = base[2 * i], t1 = base[2 * i + 1];
        base[2 * i]     = t0 * c - t1 * s;
        base[2 * i + 1] = t0 * s + t1 * c;
    }
}

// ---------------- TF32 tensor-core GEMM 128x128x16 ----------------
// mode: 0 = plain, 1 = silu(acc), 2 = acc * aux[idx], 3 = acc + aux[idx]
// blockIdx.z selects (B0,O0) vs (B1,O1).
// smem: A row-major stride 20 (conflict-free A-frag LDS),
//       B row-major stride 136 (conflict-free B-frag LDS), double-buffered.
__global__ void __launch_bounds__(256, 2) gemm_tf32_kernel(
    const float* __restrict__ A,
    const float* __restrict__ B0, const float* __restrict__ B1,
    const float* __restrict__ aux,
    float* __restrict__ O0, float* __restrict__ O1,
    int N, int K, int mode) {
    const float* Bm = blockIdx.z ? B1 : B0;
    float*       O  = blockIdx.z ? O1 : O0;

    __shared__ float As[2][128][20];
    __shared__ float Bs[2][16][136];

    const int tid  = threadIdx.x;
    const int lane = tid & 31;
    const int warp = tid >> 5;
    const int wm   = warp & 1;    // 0..1  -> rows wm*64
    const int wn   = warp >> 1;   // 0..3  -> cols wn*32
    const int rowBase = blockIdx.y * 128;
    const int colBase = blockIdx.x * 128;

    const int ar  = tid >> 1;            // 0..127 (A row)
    const int ac  = (tid & 1) * 8;       // 0 or 8 (A col chunk)
    const int bkr = tid >> 4;            // 0..15  (B k row)
    const int bnc = (tid & 15) * 4;      // 0..60  (B col chunk)

    const int lq = lane >> 2;            // 0..7
    const int lr = lane & 3;             // 0..3

    float acc[4][4][4];
#pragma unroll
    for (int i = 0; i < 4; i++)
#pragma unroll
        for (int j = 0; j < 4; j++)
#pragma unroll
            for (int t = 0; t < 4; t++) acc[i][j][t] = 0.f;

    float4 pa0, pa1, pb0, pb1;
    const int T = K / 16;

    // preload tile 0
    {
        const float* Ap = A + (size_t)(rowBase + ar) * K + ac;
        pa0 = *(const float4*)(Ap);
        pa1 = *(const float4*)(Ap + 4);
        const float* Bp = Bm + (size_t)bkr * N + colBase + bnc;
        pb0 = *(const float4*)(Bp);
        pb1 = *(const float4*)(Bp + 64);
    }
    *(float4*)&As[0][ar][ac]       = tf32r4(pa0);
    *(float4*)&As[0][ar][ac + 4]   = tf32r4(pa1);
    *(float4*)&Bs[0][bkr][bnc]     = tf32r4(pb0);
    *(float4*)&Bs[0][bkr][bnc + 64]= tf32r4(pb1);
    __syncthreads();

    for (int t = 0; t < T; t++) {
        if (t + 1 < T) {
            const float* Ap = A + (size_t)(rowBase + ar) * K + (t + 1) * 16 + ac;
            pa0 = *(const float4*)(Ap);
            pa1 = *(const float4*)(Ap + 4);
            const float* Bp = Bm + (size_t)((t + 1) * 16 + bkr) * N + colBase + bnc;
            pb0 = *(const float4*)(Bp);
            pb1 = *(const float4*)(Bp + 64);
        }
        const int buf = t & 1;
#pragma unroll
        for (int kf = 0; kf < 2; kf++) {
            const int k0 = kf * 8;
            uint32_t af[4][4];
#pragma unroll
            for (int mf = 0; mf < 4; mf++) {
                int row0 = wm * 64 + mf * 16 + lq;
                af[mf][0] = FU(As[buf][row0    ][k0 + lr]);
                af[mf][1] = FU(As[buf][row0 + 8][k0 + lr]);
                af[mf][2] = FU(As[buf][row0    ][k0 + lr + 4]);
                af[mf][3] = FU(As[buf][row0 + 8][k0 + lr + 4]);
            }
#pragma unroll
            for (int nf = 0; nf < 4; nf++) {
                int col0 = wn * 32 + nf * 8 + lq;
                uint32_t b0 = FU(Bs[buf][k0 + lr    ][col0]);
                uint32_t b1 = FU(Bs[buf][k0 + lr + 4][col0]);
#pragma unroll
                for (int mf = 0; mf < 4; mf++)
                    mma_tf32(acc[mf][nf], af[mf][0], af[mf][1], af[mf][2], af[mf][3], b0, b1);
            }
        }
        if (t + 1 < T) {
            const int nbuf = buf ^ 1;
            *(float4*)&As[nbuf][ar][ac]        = tf32r4(pa0);
            *(float4*)&As[nbuf][ar][ac + 4]    = tf32r4(pa1);
            *(float4*)&Bs[nbuf][bkr][bnc]      = tf32r4(pb0);
            *(float4*)&Bs[nbuf][bkr][bnc + 64] = tf32r4(pb1);
        }
        __syncthreads();
    }

    // epilogue
#pragma unroll
    for (int mf = 0; mf < 4; mf++) {
        int row0 = rowBase + wm * 64 + mf * 16 + lq;
#pragma unroll
        for (int nf = 0; nf < 4; nf++) {
            int col = colBase + wn * 32 + nf * 8 + 2 * lr;
#pragma unroll
            for (int half = 0; half < 2; half++) {
                int row = row0 + half * 8;
                size_t idx = (size_t)row * N + col;
                float v0 = acc[mf][nf][half * 2];
                float v1 = acc[mf][nf][half * 2 + 1];
                if (mode == 1) {
                    v0 = v0 / (1.f + __expf(-v0));
                    v1 = v1 / (1.f + __expf(-v1));
                } else if (mode == 2) {
                    v0 *= aux[idx]; v1 *= aux[idx + 1];
                } else if (mode == 3) {
                    v0 += aux[idx]; v1 += aux[idx + 1];
                }
                float2 o2 = make_float2(v0, v1);
                *(float2*)(O + idx) = o2;
            }
        }
    }
}

// ---------------- Flash attention, TF32 mma (causal, GQA) ----------------
#define AT_PAD 72
#define FLASH_SMEM (4 * 64 * AT_PAD * 4)   // Qs, Ks, Vs, Ps

__global__ void __launch_bounds__(128) flash_tf32_kernel(
    const float* __restrict__ q, const float* __restrict__ k,
    const float* __restrict__ v, float* __restrict__ o) {
    extern __shared__ float sm[];
    float* Qs = sm;
    float* Ks = sm + 64 * AT_PAD;
    float* Vs = sm + 2 * 64 * AT_PAD;
    float* Ps = sm + 3 * 64 * AT_PAD;

    const int qb  = (gridDim.x - 1) - blockIdx.x;   // heavy blocks first
    const int bh  = blockIdx.y;
    const int b   = bh / NH;
    const int h   = bh % NH;
    const int kvh = h / (NH / NKV);
    const int tid  = threadIdx.x;
    const int lane = tid & 31;
    const int warp = tid >> 5;
    const int lq = lane >> 2;     // 0..7
    const int lr = lane & 3;      // 0..3

    // load Q tile [64 x 64] (cvt to tf32)
    for (int t = tid; t < 64 * 16; t += 128) {
        int r = t >> 4, c4 = (t & 15) << 2;
        float4 vv = *(const float4*)(q + ((size_t)((b * S_LEN + qb * 64 + r) * NH + h)) * HDIM + c4);
        vv = tf32r4(vv);
        float* dst = Qs + r * AT_PAD + c4;
        dst[0] = vv.x; dst[1] = vv.y; dst[2] = vv.z; dst[3] = vv.w;
    }

    const int r0l = warp * 16 + lq;     // local q row (and +8)
    const int qrow0 = qb * 64 + r0l;
    const int qrow1 = qrow0 + 8;

    float m0 = -1e30f, m1 = -1e30f, l0 = 0.f, l1 = 0.f;
    float oacc[8][4];
#pragma unroll
    for (int nf = 0; nf < 8; nf++)
#pragma unroll
        for (int t = 0; t < 4; t++) oacc[nf][t] = 0.f;

    for (int kb = 0; kb <= qb; kb++) {
        __syncthreads();   // all warps done with previous Ks/Vs
        for (int t = tid; t < 64 * 16; t += 128) {
            int r = t >> 4, c4 = (t & 15) << 2;
            size_t goff = ((size_t)((b * S_LEN + kb * 64 + r) * NKV + kvh)) * HDIM + c4;
            float4 k4 = tf32r4(*(const float4*)(k + goff));
            float* kd = Ks + r * AT_PAD + c4;
            kd[0] = k4.x; kd[1] = k4.y; kd[2] = k4.z; kd[3] = k4.w;
            float4 v4 = tf32r4(*(const float4*)(v + goff));
            float* vd = Vs + r * AT_PAD + c4;
            vd[0] = v4.x; vd[1] = v4.y; vd[2] = v4.z; vd[3] = v4.w;
        }
        __syncthreads();

        // ---- S = Q K^T (16 x 64 per warp) ----
        float sacc[8][4];
#pragma unroll
        for (int nf = 0; nf < 8; nf++)
#pragma unroll
            for (int t = 0; t < 4; t++) sacc[nf][t] = 0.f;

#pragma unroll
        for (int kf = 0; kf < 8; kf++) {
            const int kk = kf * 8 + lr;
            uint32_t a0 = FU(Qs[r0l * AT_PAD + kk]);
            uint32_t a1 = FU(Qs[(r0l + 8) * AT_PAD + kk]);
            uint32_t a2 = FU(Qs[r0l * AT_PAD + kk + 4]);
            uint32_t a3 = FU(Qs[(r0l + 8) * AT_PAD + kk + 4]);
#pragma unroll
            for (int nf = 0; nf < 8; nf++) {
                int j = nf * 8 + lq;
                uint32_t b0 = FU(Ks[j * AT_PAD + kk]);
                uint32_t b1 = FU(Ks[j * AT_PAD + kk + 4]);
                mma_tf32(sacc[nf], a0, a1, a2, a3, b0, b1);
            }
        }

        // ---- scale, mask, online softmax ----
        const bool diag = (kb == qb);
        float rmax0 = -1e30f, rmax1 = -1e30f;
#pragma unroll
        for (int nf = 0; nf < 8; nf++) {
            int jc = kb * 64 + nf * 8 + 2 * lr;
            float s0 = sacc[nf][0] * 0.125f;
            float s1 = sacc[nf][1] * 0.125f;
            float s2 = sacc[nf][2] * 0.125f;
            float s3 = sacc[nf][3] * 0.125f;
            if (diag) {
                if (jc     > qrow0) s0 = -1e30f;
                if (jc + 1 > qrow0) s1 = -1e30f;
                if (jc     > qrow1) s2 = -1e30f;
                if (jc + 1 > qrow1) s3 = -1e30f;
            }
            sacc[nf][0] = s0; sacc[nf][1] = s1; sacc[nf][2] = s2; sacc[nf][3] = s3;
            rmax0 = fmaxf(rmax0, fmaxf(s0, s1));
            rmax1 = fmaxf(rmax1, fmaxf(s2, s3));
        }
        rmax0 = fmaxf(rmax0, __shfl_xor_sync(0xffffffffu, rmax0, 1));
        rmax0 = fmaxf(rmax0, __shfl_xor_sync(0xffffffffu, rmax0, 2));
        rmax1 = fmaxf(rmax1, __shfl_xor_sync(0xffffffffu, rmax1, 1));
        rmax1 = fmaxf(rmax1, __shfl_xor_sync(0xffffffffu, rmax1, 2));

        float mn0 = fmaxf(m0, rmax0);
        float mn1 = fmaxf(m1, rmax1);
        float alpha0 = __expf(m0 - mn0);
        float alpha1 = __expf(m1 - mn1);
        m0 = mn0; m1 = mn1;

        float rsum0 = 0.f, rsum1 = 0.f;
#pragma unroll
        for (int nf = 0; nf < 8; nf++) {
            float p0 = __expf(sacc[nf][0] - mn0);
            float p1 = __expf(sacc[nf][1] - mn0);
            float p2 = __expf(sacc[nf][2] - mn1);
            float p3 = __expf(sacc[nf][3] - mn1);
            sacc[nf][0] = p0; sacc[nf][1] = p1; sacc[nf][2] = p2; sacc[nf][3] = p3;
            rsum0 += p0 + p1;
            rsum1 += p2 + p3;
        }
        rsum0 += __shfl_xor_sync(0xffffffffu, rsum0, 1);
        rsum0 += __shfl_xor_sync(0xffffffffu, rsum0, 2);
        rsum1 += __shfl_xor_sync(0xffffffffu, rsum1, 1);
        rsum1 += __shfl_xor_sync(0xffffffffu, rsum1, 2);
        l0 = l0 * alpha0 + rsum0;
        l1 = l1 * alpha1 + rsum1;

#pragma unroll
        for (int nf = 0; nf < 8; nf++) {
            oacc[nf][0] *= alpha0; oacc[nf][1] *= alpha0;
            oacc[nf][2] *= alpha1; oacc[nf][3] *= alpha1;
        }

        // ---- stage P (tf32) to smem for PV mma ----
#pragma unroll
        for (int nf = 0; nf < 8; nf++) {
            int pc = nf * 8 + 2 * lr;
            float* p0 = Ps + r0l * AT_PAD + pc;
            p0[0] = tf32r(sacc[nf][0]); p0[1] = tf32r(sacc[nf][1]);
            float* p1 = Ps + (r0l + 8) * AT_PAD + pc;
            p1[0] = tf32r(sacc[nf][2]); p1[1] = tf32r(sacc[nf][3]);
        }
        __syncwarp();

        // ---- O += P V ----
#pragma unroll
        for (int kf = 0; kf < 8; kf++) {
            const int kk = kf * 8 + lr;
            uint32_t a0 = FU(Ps[r0l * AT_PAD + kk]);
            uint32_t a1 = FU(Ps[(r0l + 8) * AT_PAD + kk]);
            uint32_t a2 = FU(Ps[r0l * AT_PAD + kk + 4]);
            uint32_t a3 = FU(Ps[(r0l + 8) * AT_PAD + kk + 4]);
#pragma unroll
            for (int nf = 0; nf < 8; nf++) {
                int d = nf * 8 + lq;
                uint32_t b0 = FU(Vs[(kf * 8 + lr) * AT_PAD + d]);
                uint32_t b1 = FU(Vs[(kf * 8 + lr + 4) * AT_PAD + d]);
                mma_tf32(oacc[nf], a0, a1, a2, a3, b0, b1);
            }
        }
    }

    // ---- epilogue ----
    float inv0 = 1.f / l0;
    float inv1 = 1.f / l1;
    int grow0 = b * S_LEN + qrow0;
    int grow1 = b * S_LEN + qrow1;
#pragma unroll
    for (int nf = 0; nf < 8; nf++) {
        int col = nf * 8 + 2 * lr;
        float2 v0 = make_float2(oacc[nf][0] * inv0, oacc[nf][1] * inv0);
        float2 v1 = make_float2(oacc[nf][2] * inv1, oacc[nf][3] * inv1);
        *(float2*)(o + ((size_t)(grow0 * NH + h)) * HDIM + col) = v0;
        *(float2*)(o + ((size_t)(grow1 * NH + h)) * HDIM + col) = v1;
    }
}

// ---------------- launch ----------------
extern "C" void kernel_launch(void* const* d_in, const int* in_sizes, int n_in,
                              void* d_out, int out_size) {
    const float* x  = (const float*)d_in[0];
    const float* Wq = (const float*)d_in[1];
    const float* Wk = (const float*)d_in[2];
    const float* Wv = (const float*)d_in[3];
    const float* Wo = (const float*)d_in[4];
    const float* an = (const float*)d_in[5];
    const float* w0 = (const float*)d_in[6];
    const float* w1 = (const float*)d_in[7];
    const float* w2 = (const float*)d_in[8];
    const float* sn = (const float*)d_in[9];
    const float* on = (const float*)d_in[10];
    float* out = (float*)d_out;

    float *h, *q, *k, *v, *att, *x1, *x2, *gate, *cosT, *sinT;
    cudaGetSymbolAddress((void**)&h,    g_h);
    cudaGetSymbolAddress((void**)&q,    g_q);
    cudaGetSymbolAddress((void**)&k,    g_k);
    cudaGetSymbolAddress((void**)&v,    g_v);
    cudaGetSymbolAddress((void**)&att,  g_att);
    cudaGetSymbolAddress((void**)&x1,   g_x1);
    cudaGetSymbolAddress((void**)&x2,   g_x2);
    cudaGetSymbolAddress((void**)&gate, g_gate);
    cudaGetSymbolAddress((void**)&cosT, g_cosT);
    cudaGetSymbolAddress((void**)&sinT, g_sinT);

    cudaFuncSetAttribute(flash_tf32_kernel,
                         cudaFuncAttributeMaxDynamicSharedMemorySize, FLASH_SMEM);

    rope_table_kernel<<<(S_LEN * 32 + 255) / 256, 256>>>(cosT, sinT);

    const dim3 gN768 (DMODEL / 128, M_TOK / 128, 1);
    const dim3 gKV   ((NKV * HDIM) / 128, M_TOK / 128, 2);
    const dim3 gFF   (FFDIM / 128, M_TOK / 128, 1);

    const float* xin = x;
    for (int l = 0; l < NLAYER; l++) {
        const float* Wq_l = Wq + (size_t)l * DMODEL * DMODEL;
        const float* Wk_l = Wk + (size_t)l * DMODEL * (NKV * HDIM);
        const float* Wv_l = Wv + (size_t)l * DMODEL * (NKV * HDIM);
        const float* Wo_l = Wo + (size_t)l * DMODEL * DMODEL;
        const float* w0_l = w0 + (size_t)l * DMODEL * FFDIM;
        const float* w1_l = w1 + (size_t)l * DMODEL * FFDIM;
        const float* w2_l = w2 + (size_t)l * FFDIM * DMODEL;

        rmsnorm_kernel<<<M_TOK, 256>>>(xin, an + l * DMODEL, h);
        gemm_tf32_kernel<<<gN768, 256>>>(h, Wq_l, Wq_l, nullptr, q, q, DMODEL, DMODEL, 0);
        gemm_tf32_kernel<<<gKV,   256>>>(h, Wk_l, Wv_l, nullptr, k, v, NKV * HDIM, DMODEL, 0);
        rope_kernel<<<M_TOK, 256>>>(q, k, cosT, sinT);
        flash_tf32_kernel<<<dim3(S_LEN / 64, BATCH * NH), 128, FLASH_SMEM>>>(q, k, v, att);
        gemm_tf32_kernel<<<gN768, 256>>>(att, Wo_l, Wo_l, xin, x1, x1, DMODEL, DMODEL, 3);
        rmsnorm_kernel<<<M_TOK, 256>>>(x1, sn + l * DMODEL, h);
        gemm_tf32_kernel<<<gFF, 256>>>(h, w0_l, w0_l, nullptr, gate, gate, FFDIM, DMODEL, 1);
        gemm_tf32_kernel<<<gFF, 256>>>(h, w1_l, w1_l, gate, gate, gate, FFDIM, DMODEL, 2);
        gemm_tf32_kernel<<<gN768, 256>>>(gate, w2_l, w2_l, x1, x2, x2, DMODEL, FFDIM, 3);
        xin = x2;
    }
    rmsnorm_kernel<<<M_TOK, 256>>>(x2, on, out);
}